// round 5
// baseline (speedup 1.0000x reference)
#include <cuda_runtime.h>
#include <math.h>

#define LCc 1024
#define LQq 512
#define NB  64
#define ND  256

// ---------------- scratch ----------------------------------------------------
__device__ float g_E[(size_t)NB * LCc * LQq];   // E = exp(S)
__device__ float g_M[(size_t)NB * LQq * ND];    // M = E^T @ C / colsum
__device__ float g_sub0[NB * LCc];
__device__ float g_sub1[NB * LQq];
__device__ float g_invrs[NB * LCc];             // 1 / rowsum(E)
__device__ float g_csum2[NB * LQq];             // colsum(E)

// ---------------- tf32 helpers ------------------------------------------------
__device__ __forceinline__ float f2tf(float f) {
    unsigned r; asm("cvt.rna.tf32.f32 %0, %1;" : "=r"(r) : "f"(f));
    return __uint_as_float(r);
}
__device__ __forceinline__ void mma8(float4& d,
        unsigned a0, unsigned a1, unsigned a2, unsigned a3,
        unsigned b0, unsigned b1) {
    asm volatile("mma.sync.aligned.m16n8k8.row.col.f32.tf32.tf32.f32 "
        "{%0,%1,%2,%3}, {%4,%5,%6,%7}, {%8,%9}, {%0,%1,%2,%3};"
        : "+f"(d.x), "+f"(d.y), "+f"(d.z), "+f"(d.w)
        : "r"(a0), "r"(a1), "r"(a2), "r"(a3), "r"(b0), "r"(b1));
}
__device__ __forceinline__ unsigned ldu(const float* p) {
    return __float_as_uint(*p);
}

// ---------------- k_init ------------------------------------------------------
__global__ void k_init() {
    int i = blockIdx.x * blockDim.x + threadIdx.x;
    if (i < NB * LQq) g_csum2[i] = 0.f;
}

// ---------------- k0: sub0 = C@w4C, sub1 = Q@w4Q ------------------------------
__global__ __launch_bounds__(256) void k0_sub(const float* __restrict__ C,
                                              const float* __restrict__ Q,
                                              const float* __restrict__ w4C,
                                              const float* __restrict__ w4Q) {
    int gw   = (blockIdx.x * blockDim.x + threadIdx.x) >> 5;
    int lane = threadIdx.x & 31;
    const float* src; const float* w; float* dst;
    if (gw < NB * LCc) {
        src = C + (size_t)gw * ND;
        w   = w4C;
        int c = gw / NB, b = gw % NB;
        dst = g_sub0 + b * LCc + c;
    } else {
        int r = gw - NB * LCc;
        if (r >= NB * LQq) return;
        src = Q + (size_t)r * ND;
        w   = w4Q;
        int q = r / NB, b = r % NB;
        dst = g_sub1 + b * LQq + q;
    }
    float acc = 0.f;
    const float4* s4 = (const float4*)src;
    const float4* w4 = (const float4*)w;
#pragma unroll
    for (int j = 0; j < 2; ++j) {
        float4 a  = s4[lane + 32 * j];
        float4 ww = w4[lane + 32 * j];
        acc += a.x * ww.x + a.y * ww.y + a.z * ww.z + a.w * ww.w;
    }
#pragma unroll
    for (int off = 16; off; off >>= 1) acc += __shfl_xor_sync(0xffffffffu, acc, off);
    if (lane == 0) *dst = acc;
}

// ---------------- k1: E = exp(C @ (wml*Q)^T + sub0 + sub1 + bias) -------------
// tensor-core tf32; CTA 128(c) x 128(q), warp 64x32, k-chunk 16 over d
__global__ __launch_bounds__(256) void k1_scores(const float* __restrict__ C,
                                                 const float* __restrict__ Q,
                                                 const float* __restrict__ w4mlu,
                                                 const float* __restrict__ bias) {
    __shared__ float As[16][132];   // [k=d][m=c]  tf32 bits
    __shared__ float Bs[16][132];   // [k=d][n=q]  tf32 bits (pre-multiplied by wml)
    __shared__ float wml[ND];
    const int b = blockIdx.z, c0 = blockIdx.y * 128, q0 = blockIdx.x * 128;
    const int tid = threadIdx.x;
    wml[tid] = w4mlu[tid];
    const int lane = tid & 31, w = tid >> 5;
    const int g = lane >> 2, t = lane & 3;
    const int mbase = (w >> 2) * 64, nbase = (w & 3) * 32;
    const int lrow = tid & 127, lks = (tid >> 7) * 8;
    const float* Ag = C + (size_t)(c0 + lrow) * (NB * ND) + (size_t)b * ND + lks;
    const float* Bg = Q + (size_t)(q0 + lrow) * (NB * ND) + (size_t)b * ND + lks;
    float4 pa0 = *(const float4*)Ag;
    float4 pa1 = *(const float4*)(Ag + 4);
    float4 pb0 = *(const float4*)Bg;
    float4 pb1 = *(const float4*)(Bg + 4);
    float4 acc[4][4] = {};
    __syncthreads();
    for (int k0 = 0; k0 < ND; k0 += 16) {
        As[lks + 0][lrow] = f2tf(pa0.x); As[lks + 1][lrow] = f2tf(pa0.y);
        As[lks + 2][lrow] = f2tf(pa0.z); As[lks + 3][lrow] = f2tf(pa0.w);
        As[lks + 4][lrow] = f2tf(pa1.x); As[lks + 5][lrow] = f2tf(pa1.y);
        As[lks + 6][lrow] = f2tf(pa1.z); As[lks + 7][lrow] = f2tf(pa1.w);
        Bs[lks + 0][lrow] = f2tf(pb0.x * wml[k0 + lks + 0]);
        Bs[lks + 1][lrow] = f2tf(pb0.y * wml[k0 + lks + 1]);
        Bs[lks + 2][lrow] = f2tf(pb0.z * wml[k0 + lks + 2]);
        Bs[lks + 3][lrow] = f2tf(pb0.w * wml[k0 + lks + 3]);
        Bs[lks + 4][lrow] = f2tf(pb1.x * wml[k0 + lks + 4]);
        Bs[lks + 5][lrow] = f2tf(pb1.y * wml[k0 + lks + 5]);
        Bs[lks + 6][lrow] = f2tf(pb1.z * wml[k0 + lks + 6]);
        Bs[lks + 7][lrow] = f2tf(pb1.w * wml[k0 + lks + 7]);
        __syncthreads();
        if (k0 + 16 < ND) {
            pa0 = *(const float4*)(Ag + k0 + 16);
            pa1 = *(const float4*)(Ag + k0 + 20);
            pb0 = *(const float4*)(Bg + k0 + 16);
            pb1 = *(const float4*)(Bg + k0 + 20);
        }
#pragma unroll
        for (int kk = 0; kk < 16; kk += 8) {
            unsigned af[4][4], bf[4][2];
#pragma unroll
            for (int mi = 0; mi < 4; ++mi) {
                int m = mbase + mi * 16 + g;
                af[mi][0] = ldu(&As[kk + t][m]);
                af[mi][1] = ldu(&As[kk + t][m + 8]);
                af[mi][2] = ldu(&As[kk + t + 4][m]);
                af[mi][3] = ldu(&As[kk + t + 4][m + 8]);
            }
#pragma unroll
            for (int ni = 0; ni < 4; ++ni) {
                int n = nbase + ni * 8 + g;
                bf[ni][0] = ldu(&Bs[kk + t][n]);
                bf[ni][1] = ldu(&Bs[kk + t + 4][n]);
            }
#pragma unroll
            for (int mi = 0; mi < 4; ++mi)
#pragma unroll
                for (int ni = 0; ni < 4; ++ni)
                    mma8(acc[mi][ni], af[mi][0], af[mi][1], af[mi][2], af[mi][3],
                         bf[ni][0], bf[ni][1]);
        }
        __syncthreads();
    }
    const float bv = bias[0];
    float s1x[4], s1y[4];
#pragma unroll
    for (int ni = 0; ni < 4; ++ni) {
        int q = q0 + nbase + ni * 8 + 2 * t;
        s1x[ni] = g_sub1[b * LQq + q];
        s1y[ni] = g_sub1[b * LQq + q + 1];
    }
#pragma unroll
    for (int mi = 0; mi < 4; ++mi) {
        int cA = c0 + mbase + mi * 16 + g;
        float s0a = g_sub0[b * LCc + cA] + bv;
        float s0b = g_sub0[b * LCc + cA + 8] + bv;
        float* r0 = g_E + ((size_t)b * LCc + cA) * LQq + q0;
        float* r1 = r0 + 8 * LQq;
#pragma unroll
        for (int ni = 0; ni < 4; ++ni) {
            int q = nbase + ni * 8 + 2 * t;
            float2 e0 = {expf(acc[mi][ni].x + s0a + s1x[ni]),
                         expf(acc[mi][ni].y + s0a + s1y[ni])};
            float2 e1 = {expf(acc[mi][ni].z + s0b + s1x[ni]),
                         expf(acc[mi][ni].w + s0b + s1y[ni])};
            *(float2*)(r0 + q) = e0;
            *(float2*)(r1 + q) = e1;
        }
    }
}

// ---------------- k23: rowsum (-> invrs) + colsum (-> csum2) -----------------
__global__ __launch_bounds__(256) void k23_sums() {
    const int b  = blockIdx.y;
    const int cb = blockIdx.x * 128;
    const int w = threadIdx.x >> 5, l = threadIdx.x & 31;
    float colacc[16] = {};
#pragma unroll 4
    for (int rr = 0; rr < 16; ++rr) {
        int c = cb + w + rr * 8;
        const float4* row = (const float4*)(g_E + ((size_t)b * LCc + c) * LQq);
        float rs = 0.f;
#pragma unroll
        for (int jj = 0; jj < 4; ++jj) {
            float4 v = row[l + 32 * jj];
            colacc[jj * 4 + 0] += v.x; colacc[jj * 4 + 1] += v.y;
            colacc[jj * 4 + 2] += v.z; colacc[jj * 4 + 3] += v.w;
            rs += v.x + v.y + v.z + v.w;
        }
#pragma unroll
        for (int off = 16; off; off >>= 1) rs += __shfl_xor_sync(0xffffffffu, rs, off);
        if (l == 0) g_invrs[b * LCc + c] = 1.0f / rs;
    }
#pragma unroll
    for (int jj = 0; jj < 4; ++jj)
#pragma unroll
        for (int tt = 0; tt < 4; ++tt)
            atomicAdd(&g_csum2[b * LQq + 4 * l + 128 * jj + tt], colacc[jj * 4 + tt]);
}

// ---------------- k4: M = E^T @ C / colsum ------------------------------------
// CTA 128(q) x 128(d), warp 64x32, k-chunk 16 over c (no transpose staging)
__global__ __launch_bounds__(256) void k4_M(const float* __restrict__ C) {
    __shared__ float As[16][132];   // [k=c][m=q]
    __shared__ float Bs[16][132];   // [k=c][n=d]
    const int b = blockIdx.z, q0 = blockIdx.y * 128, d0 = blockIdx.x * 128;
    const int tid = threadIdx.x;
    const int lane = tid & 31, w = tid >> 5;
    const int g = lane >> 2, t = lane & 3;
    const int mbase = (w >> 2) * 64, nbase = (w & 3) * 32;
    const int l4 = (lane) * 4 % 128;        // (tid & 31) * 4
    const int crr = tid >> 5;               // 0..7
    const float* Ag = g_E + ((size_t)b * LCc + crr) * LQq + q0 + l4;
    const float* Bg = C + (size_t)crr * (NB * ND) + (size_t)b * ND + d0 + l4;
    float4 pa0 = *(const float4*)Ag;
    float4 pa1 = *(const float4*)(Ag + (size_t)8 * LQq);
    float4 pb0 = *(const float4*)Bg;
    float4 pb1 = *(const float4*)(Bg + (size_t)8 * (NB * ND));
    float4 acc[4][4] = {};
    for (int cb = 0; cb < LCc; cb += 16) {
        float4 ta = {f2tf(pa0.x), f2tf(pa0.y), f2tf(pa0.z), f2tf(pa0.w)};
        *(float4*)&As[crr][l4] = ta;
        ta = make_float4(f2tf(pa1.x), f2tf(pa1.y), f2tf(pa1.z), f2tf(pa1.w));
        *(float4*)&As[crr + 8][l4] = ta;
        ta = make_float4(f2tf(pb0.x), f2tf(pb0.y), f2tf(pb0.z), f2tf(pb0.w));
        *(float4*)&Bs[crr][l4] = ta;
        ta = make_float4(f2tf(pb1.x), f2tf(pb1.y), f2tf(pb1.z), f2tf(pb1.w));
        *(float4*)&Bs[crr + 8][l4] = ta;
        __syncthreads();
        if (cb + 16 < LCc) {
            pa0 = *(const float4*)(Ag + (size_t)(cb + 16) * LQq);
            pa1 = *(const float4*)(Ag + (size_t)(cb + 24) * LQq);
            pb0 = *(const float4*)(Bg + (size_t)(cb + 16) * (NB * ND));
            pb1 = *(const float4*)(Bg + (size_t)(cb + 24) * (NB * ND));
        }
#pragma unroll
        for (int kk = 0; kk < 16; kk += 8) {
            unsigned af[4][4], bf[4][2];
#pragma unroll
            for (int mi = 0; mi < 4; ++mi) {
                int m = mbase + mi * 16 + g;
                af[mi][0] = ldu(&As[kk + t][m]);
                af[mi][1] = ldu(&As[kk + t][m + 8]);
                af[mi][2] = ldu(&As[kk + t + 4][m]);
                af[mi][3] = ldu(&As[kk + t + 4][m + 8]);
            }
#pragma unroll
            for (int ni = 0; ni < 4; ++ni) {
                int n = nbase + ni * 8 + g;
                bf[ni][0] = ldu(&Bs[kk + t][n]);
                bf[ni][1] = ldu(&Bs[kk + t + 4][n]);
            }
#pragma unroll
            for (int mi = 0; mi < 4; ++mi)
#pragma unroll
                for (int ni = 0; ni < 4; ++ni)
                    mma8(acc[mi][ni], af[mi][0], af[mi][1], af[mi][2], af[mi][3],
                         bf[ni][0], bf[ni][1]);
        }
        __syncthreads();
    }
#pragma unroll
    for (int mi = 0; mi < 4; ++mi) {
        int qA = q0 + mbase + mi * 16 + g;
        float i0 = 1.0f / g_csum2[b * LQq + qA];
        float i1 = 1.0f / g_csum2[b * LQq + qA + 8];
        float* r0 = g_M + ((size_t)b * LQq + qA) * ND + d0;
        float* r1 = r0 + 8 * ND;
#pragma unroll
        for (int ni = 0; ni < 4; ++ni) {
            int d = nbase + ni * 8 + 2 * t;
            float2 o0 = {acc[mi][ni].x * i0, acc[mi][ni].y * i0};
            float2 o1 = {acc[mi][ni].z * i1, acc[mi][ni].w * i1};
            *(float2*)(r0 + d) = o0;
            *(float2*)(r1 + d) = o1;
        }
    }
}

// ---------------- k5: A = S1@Q, B_ = S1@M, fused transposed-concat ------------
// CTA 128(c) x 64(d), warp 32x32 dual-output, k-chunk 16 over q
__global__ __launch_bounds__(256) void k5_out(const float* __restrict__ C,
                                              const float* __restrict__ Q,
                                              float* __restrict__ out) {
    __shared__ __align__(16) float smem[8576];
    float (*As)[132] = (float(*)[132])smem;           // [k=q 16][c 128]
    float (*Bq)[68]  = (float(*)[68])(smem + 2112);   // [k=q 16][d 64]
    float (*Bm)[68]  = (float(*)[68])(smem + 3200);
    float (*Cs)[65]  = (float(*)[65])smem;            // epilogue: [d][c]
    float (*Tr)[69]  = (float(*)[69])(smem + 4160);   // epilogue: [c][d]
    const int b = blockIdx.z, c0 = blockIdx.y * 128, d0 = blockIdx.x * 64;
    const int tid = threadIdx.x;
    const int lane = tid & 31, w = tid >> 5;
    const int g = lane >> 2, t = lane & 3;
    const int wr = w >> 1, wc = w & 1;
    const int mbase = wr * 32, nbase = wc * 32;
    const int lrow = tid & 127, lks = (tid >> 7) * 8;
    const int qr = tid >> 4, dl = (tid & 15) * 4;
    const float* Ag = g_E + ((size_t)b * LCc + c0 + lrow) * LQq + lks;
    const float* Qg = Q + (size_t)b * ND + d0 + dl;
    const float* Mg = g_M + (size_t)b * LQq * ND + d0 + dl;
    float4 pa0 = *(const float4*)Ag;
    float4 pa1 = *(const float4*)(Ag + 4);
    float4 pq  = *(const float4*)(Qg + (size_t)qr * (NB * ND));
    float4 pm  = *(const float4*)(Mg + (size_t)qr * ND);
    float4 accA[2][4] = {}, accB[2][4] = {};
    for (int k0 = 0; k0 < LQq; k0 += 16) {
        As[lks + 0][lrow] = f2tf(pa0.x); As[lks + 1][lrow] = f2tf(pa0.y);
        As[lks + 2][lrow] = f2tf(pa0.z); As[lks + 3][lrow] = f2tf(pa0.w);
        As[lks + 4][lrow] = f2tf(pa1.x); As[lks + 5][lrow] = f2tf(pa1.y);
        As[lks + 6][lrow] = f2tf(pa1.z); As[lks + 7][lrow] = f2tf(pa1.w);
        float4 tq = {f2tf(pq.x), f2tf(pq.y), f2tf(pq.z), f2tf(pq.w)};
        *(float4*)&Bq[qr][dl] = tq;
        float4 tm = {f2tf(pm.x), f2tf(pm.y), f2tf(pm.z), f2tf(pm.w)};
        *(float4*)&Bm[qr][dl] = tm;
        __syncthreads();
        if (k0 + 16 < LQq) {
            pa0 = *(const float4*)(Ag + k0 + 16);
            pa1 = *(const float4*)(Ag + k0 + 20);
            pq  = *(const float4*)(Qg + (size_t)(k0 + 16 + qr) * (NB * ND));
            pm  = *(const float4*)(Mg + (size_t)(k0 + 16 + qr) * ND);
        }
#pragma unroll
        for (int kk = 0; kk < 16; kk += 8) {
            unsigned af[2][4], qf[4][2], mf[4][2];
#pragma unroll
            for (int mi = 0; mi < 2; ++mi) {
                int m = mbase + mi * 16 + g;
                af[mi][0] = ldu(&As[kk + t][m]);
                af[mi][1] = ldu(&As[kk + t][m + 8]);
                af[mi][2] = ldu(&As[kk + t + 4][m]);
                af[mi][3] = ldu(&As[kk + t + 4][m + 8]);
            }
#pragma unroll
            for (int ni = 0; ni < 4; ++ni) {
                int n = nbase + ni * 8 + g;
                qf[ni][0] = ldu(&Bq[kk + t][n]);
                qf[ni][1] = ldu(&Bq[kk + t + 4][n]);
                mf[ni][0] = ldu(&Bm[kk + t][n]);
                mf[ni][1] = ldu(&Bm[kk + t + 4][n]);
            }
#pragma unroll
            for (int mi = 0; mi < 2; ++mi)
#pragma unroll
                for (int ni = 0; ni < 4; ++ni) {
                    mma8(accA[mi][ni], af[mi][0], af[mi][1], af[mi][2], af[mi][3],
                         qf[ni][0], qf[ni][1]);
                    mma8(accB[mi][ni], af[mi][0], af[mi][1], af[mi][2], af[mi][3],
                         mf[ni][0], mf[ni][1]);
                }
        }
        __syncthreads();
    }
#pragma unroll
    for (int mi = 0; mi < 2; ++mi) {
        int cA = c0 + mbase + mi * 16 + g;
        float i0 = g_invrs[b * LCc + cA];
        float i1 = g_invrs[b * LCc + cA + 8];
#pragma unroll
        for (int ni = 0; ni < 4; ++ni) {
            accA[mi][ni].x *= i0; accA[mi][ni].y *= i0;
            accA[mi][ni].z *= i1; accA[mi][ni].w *= i1;
            accB[mi][ni].x *= i0; accB[mi][ni].y *= i0;
            accB[mi][ni].z *= i1; accB[mi][ni].w *= i1;
        }
    }
    const int cl = tid & 63, dseg = (tid >> 6) * 16;
    const int cr = tid & 63, db = tid >> 6;
    const size_t ob = (size_t)b * (4 * ND) * LCc;
    for (int h = 0; h < 2; ++h) {
        __syncthreads();
        {   // load C tile: Cs[d][c] = C[c0+h*64+cl, b, d0+d]
            const float* Cg = C + (size_t)(c0 + h * 64 + cl) * (NB * ND) + (size_t)b * ND + d0 + dseg;
#pragma unroll
            for (int dd = 0; dd < 16; dd += 4) {
                float4 cv = *(const float4*)(Cg + dd);
                Cs[dseg + dd + 0][cl] = cv.x; Cs[dseg + dd + 1][cl] = cv.y;
                Cs[dseg + dd + 2][cl] = cv.z; Cs[dseg + dd + 3][cl] = cv.w;
            }
        }
        if ((w >> 2) == h) {
#pragma unroll
            for (int mi = 0; mi < 2; ++mi) {
                int clh = (wr & 1) * 32 + mi * 16 + g;
#pragma unroll
                for (int ni = 0; ni < 4; ++ni) {
                    int d = nbase + ni * 8 + 2 * t;
                    Tr[clh][d]     = accA[mi][ni].x;
                    Tr[clh][d + 1] = accA[mi][ni].y;
                    Tr[clh + 8][d]     = accA[mi][ni].z;
                    Tr[clh + 8][d + 1] = accA[mi][ni].w;
                }
            }
        }
        __syncthreads();
#pragma unroll
        for (int rr = 0; rr < 16; ++rr) {
            int dr = db + rr * 4;
            float cval = Cs[dr][cr];
            float aval = Tr[cr][dr];
            size_t col = (size_t)(c0 + h * 64 + cr);
            out[ob + (size_t)(d0 + dr) * LCc + col]          = cval;
            out[ob + (size_t)(ND + d0 + dr) * LCc + col]     = aval;
            out[ob + (size_t)(2 * ND + d0 + dr) * LCc + col] = cval * aval;
        }
        __syncthreads();
        if ((w >> 2) == h) {
#pragma unroll
            for (int mi = 0; mi < 2; ++mi) {
                int clh = (wr & 1) * 32 + mi * 16 + g;
#pragma unroll
                for (int ni = 0; ni < 4; ++ni) {
                    int d = nbase + ni * 8 + 2 * t;
                    Tr[clh][d]     = accB[mi][ni].x;
                    Tr[clh][d + 1] = accB[mi][ni].y;
                    Tr[clh + 8][d]     = accB[mi][ni].z;
                    Tr[clh + 8][d + 1] = accB[mi][ni].w;
                }
            }
        }
        __syncthreads();
#pragma unroll
        for (int rr = 0; rr < 16; ++rr) {
            int dr = db + rr * 4;
            out[ob + (size_t)(3 * ND + d0 + dr) * LCc + (size_t)(c0 + h * 64 + cr)] =
                Cs[dr][cr] * Tr[cr][dr];
        }
    }
}

// ------------------------------------------------------------------------------
extern "C" void kernel_launch(void* const* d_in, const int* in_sizes, int n_in,
                              void* d_out, int out_size) {
    const float* C     = (const float*)d_in[0];
    const float* Q     = (const float*)d_in[1];
    const float* w4C   = (const float*)d_in[2];
    const float* w4Q   = (const float*)d_in[3];
    const float* w4mlu = (const float*)d_in[4];
    const float* bias  = (const float*)d_in[5];
    float* out = (float*)d_out;

    k_init<<<(NB * LQq + 255) / 256, 256>>>();
    k0_sub<<<(NB * LCc + NB * LQq) / 8, 256>>>(C, Q, w4C, w4Q);
    k1_scores<<<dim3(LQq / 128, LCc / 128, NB), 256>>>(C, Q, w4mlu, bias);
    k23_sums<<<dim3(LCc / 128, NB), 256>>>();
    k4_M<<<dim3(ND / 128, LQq / 128, NB), 256>>>(C);
    k5_out<<<dim3(ND / 64, LCc / 128, NB), 256>>>(C, Q, out);
}

// round 6
// speedup vs baseline: 1.0828x; 1.0828x over previous
#include <cuda_runtime.h>
#include <math.h>

#define LCc 1024
#define LQq 512
#define NB  64
#define ND  256

__device__ float g_E[(size_t)NB * LCc * LQq];
__device__ float g_M[(size_t)NB * LQq * ND];
__device__ float g_sub0[NB * LCc];
__device__ float g_sub1[NB * LQq];
__device__ float g_rsum[NB * LCc];
__device__ float g_invrs[NB * LCc];
__device__ float g_csum2[NB * LQq];

__device__ __forceinline__ float f2tf(float f) {
    unsigned r; asm("cvt.rna.tf32.f32 %0, %1;" : "=r"(r) : "f"(f));
    return __uint_as_float(r);
}
__device__ __forceinline__ void mma8(float4& d,
        unsigned a0, unsigned a1, unsigned a2, unsigned a3,
        unsigned b0, unsigned b1) {
    asm volatile("mma.sync.aligned.m16n8k8.row.col.f32.tf32.tf32.f32 "
        "{%0,%1,%2,%3}, {%4,%5,%6,%7}, {%8,%9}, {%0,%1,%2,%3};"
        : "+f"(d.x), "+f"(d.y), "+f"(d.z), "+f"(d.w)
        : "r"(a0), "r"(a1), "r"(a2), "r"(a3), "r"(b0), "r"(b1));
}
__device__ __forceinline__ unsigned ldu(const float* p) { return __float_as_uint(*p); }

__global__ void k_init() {
    int i = blockIdx.x * blockDim.x + threadIdx.x;
    if (i < NB * LQq) g_csum2[i] = 0.f;
    if (i < NB * LCc) g_rsum[i] = 0.f;
}
__global__ void k_fin() {
    int i = blockIdx.x * blockDim.x + threadIdx.x;
    if (i < NB * LCc) g_invrs[i] = 1.0f / g_rsum[i];
}

__global__ __launch_bounds__(256) void k0_sub(const float* __restrict__ C,
                                              const float* __restrict__ Q,
                                              const float* __restrict__ w4C,
                                              const float* __restrict__ w4Q) {
    int gw   = (blockIdx.x * blockDim.x + threadIdx.x) >> 5;
    int lane = threadIdx.x & 31;
    const float* src; const float* w; float* dst;
    if (gw < NB * LCc) {
        src = C + (size_t)gw * ND; w = w4C;
        int c = gw / NB, b = gw % NB;
        dst = g_sub0 + b * LCc + c;
    } else {
        int r = gw - NB * LCc;
        if (r >= NB * LQq) return;
        src = Q + (size_t)r * ND; w = w4Q;
        int q = r / NB, b = r % NB;
        dst = g_sub1 + b * LQq + q;
    }
    float acc = 0.f;
    const float4* s4 = (const float4*)src;
    const float4* w4 = (const float4*)w;
#pragma unroll
    for (int j = 0; j < 2; ++j) {
        float4 a = s4[lane + 32 * j], ww = w4[lane + 32 * j];
        acc += a.x * ww.x + a.y * ww.y + a.z * ww.z + a.w * ww.w;
    }
#pragma unroll
    for (int off = 16; off; off >>= 1) acc += __shfl_xor_sync(0xffffffffu, acc, off);
    if (lane == 0) *dst = acc;
}

// ---- k1: E = exp(C @ (wml*Q)^T + sub0 + sub1 + bias); fused row/col sums ----
__global__ __launch_bounds__(256) void k1_scores(const float* __restrict__ C,
                                                 const float* __restrict__ Q,
                                                 const float* __restrict__ w4mlu,
                                                 const float* __restrict__ bias) {
    __shared__ float As[2][16][136];
    __shared__ float Bs[2][16][136];
    __shared__ float wml[ND];
    const int b = blockIdx.z, c0 = blockIdx.y * 128, q0 = blockIdx.x * 128;
    const int tid = threadIdx.x;
    wml[tid] = w4mlu[tid];
    const int lane = tid & 31, w = tid >> 5;
    const int g = lane >> 2, t = lane & 3;
    const int mbase = (w >> 2) * 64, nbase = (w & 3) * 32;
    const int lrow = tid & 127, lks = (tid >> 7) * 8;
    const float* Ag = C + (size_t)(c0 + lrow) * (NB * ND) + (size_t)b * ND + lks;
    const float* Bg = Q + (size_t)(q0 + lrow) * (NB * ND) + (size_t)b * ND + lks;
    float4 pa0 = *(const float4*)Ag, pa1 = *(const float4*)(Ag + 4);
    float4 pb0 = *(const float4*)Bg, pb1 = *(const float4*)(Bg + 4);
    float4 acc[4][4] = {};
    __syncthreads();   // wml ready
    {   // stage chunk 0 -> buf 0
        As[0][lks + 0][lrow] = f2tf(pa0.x); As[0][lks + 1][lrow] = f2tf(pa0.y);
        As[0][lks + 2][lrow] = f2tf(pa0.z); As[0][lks + 3][lrow] = f2tf(pa0.w);
        As[0][lks + 4][lrow] = f2tf(pa1.x); As[0][lks + 5][lrow] = f2tf(pa1.y);
        As[0][lks + 6][lrow] = f2tf(pa1.z); As[0][lks + 7][lrow] = f2tf(pa1.w);
        Bs[0][lks + 0][lrow] = f2tf(pb0.x * wml[lks + 0]);
        Bs[0][lks + 1][lrow] = f2tf(pb0.y * wml[lks + 1]);
        Bs[0][lks + 2][lrow] = f2tf(pb0.z * wml[lks + 2]);
        Bs[0][lks + 3][lrow] = f2tf(pb0.w * wml[lks + 3]);
        Bs[0][lks + 4][lrow] = f2tf(pb1.x * wml[lks + 4]);
        Bs[0][lks + 5][lrow] = f2tf(pb1.y * wml[lks + 5]);
        Bs[0][lks + 6][lrow] = f2tf(pb1.z * wml[lks + 6]);
        Bs[0][lks + 7][lrow] = f2tf(pb1.w * wml[lks + 7]);
    }
    __syncthreads();
    int p = 0;
    for (int k0 = 0; k0 < ND; k0 += 16) {
        const bool nxt = (k0 + 16) < ND;
        if (nxt) {
            pa0 = *(const float4*)(Ag + k0 + 16); pa1 = *(const float4*)(Ag + k0 + 20);
            pb0 = *(const float4*)(Bg + k0 + 16); pb1 = *(const float4*)(Bg + k0 + 20);
        }
#pragma unroll
        for (int kk = 0; kk < 16; kk += 8) {
            unsigned af[4][4], bf[4][2];
#pragma unroll
            for (int mi = 0; mi < 4; ++mi) {
                int m = mbase + mi * 16 + g;
                af[mi][0] = ldu(&As[p][kk + t][m]);     af[mi][1] = ldu(&As[p][kk + t][m + 8]);
                af[mi][2] = ldu(&As[p][kk + t + 4][m]); af[mi][3] = ldu(&As[p][kk + t + 4][m + 8]);
            }
#pragma unroll
            for (int ni = 0; ni < 4; ++ni) {
                int n = nbase + ni * 8 + g;
                bf[ni][0] = ldu(&Bs[p][kk + t][n]); bf[ni][1] = ldu(&Bs[p][kk + t + 4][n]);
            }
#pragma unroll
            for (int mi = 0; mi < 4; ++mi)
#pragma unroll
                for (int ni = 0; ni < 4; ++ni)
                    mma8(acc[mi][ni], af[mi][0], af[mi][1], af[mi][2], af[mi][3],
                         bf[ni][0], bf[ni][1]);
        }
        if (nxt) {
            const int kb = k0 + 16, q2 = p ^ 1;
            As[q2][lks + 0][lrow] = f2tf(pa0.x); As[q2][lks + 1][lrow] = f2tf(pa0.y);
            As[q2][lks + 2][lrow] = f2tf(pa0.z); As[q2][lks + 3][lrow] = f2tf(pa0.w);
            As[q2][lks + 4][lrow] = f2tf(pa1.x); As[q2][lks + 5][lrow] = f2tf(pa1.y);
            As[q2][lks + 6][lrow] = f2tf(pa1.z); As[q2][lks + 7][lrow] = f2tf(pa1.w);
            Bs[q2][lks + 0][lrow] = f2tf(pb0.x * wml[kb + lks + 0]);
            Bs[q2][lks + 1][lrow] = f2tf(pb0.y * wml[kb + lks + 1]);
            Bs[q2][lks + 2][lrow] = f2tf(pb0.z * wml[kb + lks + 2]);
            Bs[q2][lks + 3][lrow] = f2tf(pb0.w * wml[kb + lks + 3]);
            Bs[q2][lks + 4][lrow] = f2tf(pb1.x * wml[kb + lks + 4]);
            Bs[q2][lks + 5][lrow] = f2tf(pb1.y * wml[kb + lks + 5]);
            Bs[q2][lks + 6][lrow] = f2tf(pb1.z * wml[kb + lks + 6]);
            Bs[q2][lks + 7][lrow] = f2tf(pb1.w * wml[kb + lks + 7]);
        }
        __syncthreads();
        p ^= 1;
    }
    const float bv = bias[0];
    float s1x[4], s1y[4];
#pragma unroll
    for (int ni = 0; ni < 4; ++ni) {
        int q = q0 + nbase + ni * 8 + 2 * t;
        s1x[ni] = g_sub1[b * LQq + q];
        s1y[ni] = g_sub1[b * LQq + q + 1];
    }
    float rs0[4] = {}, rs1[4] = {}, ccx[4] = {}, ccy[4] = {};
#pragma unroll
    for (int mi = 0; mi < 4; ++mi) {
        int cA = c0 + mbase + mi * 16 + g;
        float s0a = g_sub0[b * LCc + cA] + bv;
        float s0b = g_sub0[b * LCc + cA + 8] + bv;
        float* r0 = g_E + ((size_t)b * LCc + cA) * LQq + q0;
        float* r1 = r0 + 8 * LQq;
#pragma unroll
        for (int ni = 0; ni < 4; ++ni) {
            int q = nbase + ni * 8 + 2 * t;
            float2 e0 = {expf(acc[mi][ni].x + s0a + s1x[ni]),
                         expf(acc[mi][ni].y + s0a + s1y[ni])};
            float2 e1 = {expf(acc[mi][ni].z + s0b + s1x[ni]),
                         expf(acc[mi][ni].w + s0b + s1y[ni])};
            *(float2*)(r0 + q) = e0;
            *(float2*)(r1 + q) = e1;
            rs0[mi] += e0.x + e0.y; rs1[mi] += e1.x + e1.y;
            ccx[ni] += e0.x + e1.x; ccy[ni] += e0.y + e1.y;
        }
    }
#pragma unroll
    for (int mi = 0; mi < 4; ++mi) {   // reduce over t (lane bits 0,1)
        float a = rs0[mi], c2 = rs1[mi];
        a  += __shfl_xor_sync(0xffffffffu, a, 1);  a  += __shfl_xor_sync(0xffffffffu, a, 2);
        c2 += __shfl_xor_sync(0xffffffffu, c2, 1); c2 += __shfl_xor_sync(0xffffffffu, c2, 2);
        if (t == 0) {
            int cA = c0 + mbase + mi * 16 + g;
            atomicAdd(&g_rsum[b * LCc + cA], a);
            atomicAdd(&g_rsum[b * LCc + cA + 8], c2);
        }
    }
#pragma unroll
    for (int ni = 0; ni < 4; ++ni) {   // reduce over g (lane bits 2,3,4)
        float x = ccx[ni], y = ccy[ni];
        x += __shfl_xor_sync(0xffffffffu, x, 4);  y += __shfl_xor_sync(0xffffffffu, y, 4);
        x += __shfl_xor_sync(0xffffffffu, x, 8);  y += __shfl_xor_sync(0xffffffffu, y, 8);
        x += __shfl_xor_sync(0xffffffffu, x, 16); y += __shfl_xor_sync(0xffffffffu, y, 16);
        if (g == 0) {
            int q = q0 + nbase + ni * 8 + 2 * t;
            atomicAdd(&g_csum2[b * LQq + q], x);
            atomicAdd(&g_csum2[b * LQq + q + 1], y);
        }
    }
}

// ---- k4: M = E^T @ C / colsum ----
__global__ __launch_bounds__(256) void k4_M(const float* __restrict__ C) {
    __shared__ float As[2][16][136];
    __shared__ float Bs[2][16][136];
    const int b = blockIdx.z, q0 = blockIdx.y * 128, d0 = blockIdx.x * 128;
    const int tid = threadIdx.x;
    const int lane = tid & 31, w = tid >> 5;
    const int g = lane >> 2, t = lane & 3;
    const int mbase = (w >> 2) * 64, nbase = (w & 3) * 32;
    const int l4 = (lane & 31) * 4 % 128;
    const int crr = tid >> 5;
    const float* Ag = g_E + ((size_t)b * LCc + crr) * LQq + q0 + l4;
    const float* Bg = C + (size_t)crr * (NB * ND) + (size_t)b * ND + d0 + l4;
    float4 pa0 = *(const float4*)Ag;
    float4 pa1 = *(const float4*)(Ag + (size_t)8 * LQq);
    float4 pb0 = *(const float4*)Bg;
    float4 pb1 = *(const float4*)(Bg + (size_t)8 * (NB * ND));
    float4 acc[4][4] = {};
    {
        *(float4*)&As[0][crr][l4]     = make_float4(f2tf(pa0.x), f2tf(pa0.y), f2tf(pa0.z), f2tf(pa0.w));
        *(float4*)&As[0][crr + 8][l4] = make_float4(f2tf(pa1.x), f2tf(pa1.y), f2tf(pa1.z), f2tf(pa1.w));
        *(float4*)&Bs[0][crr][l4]     = make_float4(f2tf(pb0.x), f2tf(pb0.y), f2tf(pb0.z), f2tf(pb0.w));
        *(float4*)&Bs[0][crr + 8][l4] = make_float4(f2tf(pb1.x), f2tf(pb1.y), f2tf(pb1.z), f2tf(pb1.w));
    }
    __syncthreads();
    int p = 0;
    for (int cb = 0; cb < LCc; cb += 16) {
        const bool nxt = (cb + 16) < LCc;
        if (nxt) {
            pa0 = *(const float4*)(Ag + (size_t)(cb + 16) * LQq);
            pa1 = *(const float4*)(Ag + (size_t)(cb + 24) * LQq);
            pb0 = *(const float4*)(Bg + (size_t)(cb + 16) * (NB * ND));
            pb1 = *(const float4*)(Bg + (size_t)(cb + 24) * (NB * ND));
        }
#pragma unroll
        for (int kk = 0; kk < 16; kk += 8) {
            unsigned af[4][4], bf[4][2];
#pragma unroll
            for (int mi = 0; mi < 4; ++mi) {
                int m = mbase + mi * 16 + g;
                af[mi][0] = ldu(&As[p][kk + t][m]);     af[mi][1] = ldu(&As[p][kk + t][m + 8]);
                af[mi][2] = ldu(&As[p][kk + t + 4][m]); af[mi][3] = ldu(&As[p][kk + t + 4][m + 8]);
            }
#pragma unroll
            for (int ni = 0; ni < 4; ++ni) {
                int n = nbase + ni * 8 + g;
                bf[ni][0] = ldu(&Bs[p][kk + t][n]); bf[ni][1] = ldu(&Bs[p][kk + t + 4][n]);
            }
#pragma unroll
            for (int mi = 0; mi < 4; ++mi)
#pragma unroll
                for (int ni = 0; ni < 4; ++ni)
                    mma8(acc[mi][ni], af[mi][0], af[mi][1], af[mi][2], af[mi][3],
                         bf[ni][0], bf[ni][1]);
        }
        if (nxt) {
            const int q2 = p ^ 1;
            *(float4*)&As[q2][crr][l4]     = make_float4(f2tf(pa0.x), f2tf(pa0.y), f2tf(pa0.z), f2tf(pa0.w));
            *(float4*)&As[q2][crr + 8][l4] = make_float4(f2tf(pa1.x), f2tf(pa1.y), f2tf(pa1.z), f2tf(pa1.w));
            *(float4*)&Bs[q2][crr][l4]     = make_float4(f2tf(pb0.x), f2tf(pb0.y), f2tf(pb0.z), f2tf(pb0.w));
            *(float4*)&Bs[q2][crr + 8][l4] = make_float4(f2tf(pb1.x), f2tf(pb1.y), f2tf(pb1.z), f2tf(pb1.w));
        }
        __syncthreads();
        p ^= 1;
    }
#pragma unroll
    for (int mi = 0; mi < 4; ++mi) {
        int qA = q0 + mbase + mi * 16 + g;
        float i0 = 1.0f / g_csum2[b * LQq + qA];
        float i1 = 1.0f / g_csum2[b * LQq + qA + 8];
        float* r0 = g_M + ((size_t)b * LQq + qA) * ND + d0;
        float* r1 = r0 + 8 * ND;
#pragma unroll
        for (int ni = 0; ni < 4; ++ni) {
            int d = nbase + ni * 8 + 2 * t;
            *(float2*)(r0 + d) = make_float2(acc[mi][ni].x * i0, acc[mi][ni].y * i0);
            *(float2*)(r1 + d) = make_float2(acc[mi][ni].z * i1, acc[mi][ni].w * i1);
        }
    }
}

// ---- k5: A = S1@Q, B_ = S1@M, fused transposed-concat ----
__global__ __launch_bounds__(256) void k5_out(const float* __restrict__ C,
                                              const float* __restrict__ Q,
                                              float* __restrict__ out) {
    __shared__ __align__(16) float smem[8960];
    float (*As)[16][136] = (float(*)[16][136])smem;            // 2*2176
    float (*Bq)[16][72]  = (float(*)[16][72])(smem + 4352);    // 2*1152
    float (*Bm)[16][72]  = (float(*)[16][72])(smem + 6656);    // 2*1152
    float (*Cs)[65]      = (float(*)[65])smem;                 // epi
    float (*Tr)[69]      = (float(*)[69])(smem + 4160);        // epi
    const int b = blockIdx.z, c0 = blockIdx.y * 128, d0 = blockIdx.x * 64;
    const int tid = threadIdx.x;
    const int lane = tid & 31, w = tid >> 5;
    const int g = lane >> 2, t = lane & 3;
    const int wr = w >> 1, wc = w & 1;
    const int mbase = wr * 32, nbase = wc * 32;
    const int lrow = tid & 127, lks = (tid >> 7) * 8;
    const int qr = tid >> 4, dl = (tid & 15) * 4;
    const float* Ag = g_E + ((size_t)b * LCc + c0 + lrow) * LQq + lks;
    const float* Qg = Q + (size_t)b * ND + d0 + dl;
    const float* Mg = g_M + (size_t)b * LQq * ND + d0 + dl;
    float4 pa0 = *(const float4*)Ag, pa1 = *(const float4*)(Ag + 4);
    float4 pq = *(const float4*)(Qg + (size_t)qr * (NB * ND));
    float4 pm = *(const float4*)(Mg + (size_t)qr * ND);
    float4 accA[2][4] = {}, accB[2][4] = {};
    {
        As[0][lks + 0][lrow] = f2tf(pa0.x); As[0][lks + 1][lrow] = f2tf(pa0.y);
        As[0][lks + 2][lrow] = f2tf(pa0.z); As[0][lks + 3][lrow] = f2tf(pa0.w);
        As[0][lks + 4][lrow] = f2tf(pa1.x); As[0][lks + 5][lrow] = f2tf(pa1.y);
        As[0][lks + 6][lrow] = f2tf(pa1.z); As[0][lks + 7][lrow] = f2tf(pa1.w);
        *(float4*)&Bq[0][qr][dl] = make_float4(f2tf(pq.x), f2tf(pq.y), f2tf(pq.z), f2tf(pq.w));
        *(float4*)&Bm[0][qr][dl] = make_float4(f2tf(pm.x), f2tf(pm.y), f2tf(pm.z), f2tf(pm.w));
    }
    __syncthreads();
    int p = 0;
    for (int k0 = 0; k0 < LQq; k0 += 16) {
        const bool nxt = (k0 + 16) < LQq;
        if (nxt) {
            pa0 = *(const float4*)(Ag + k0 + 16); pa1 = *(const float4*)(Ag + k0 + 20);
            pq = *(const float4*)(Qg + (size_t)(k0 + 16 + qr) * (NB * ND));
            pm = *(const float4*)(Mg + (size_t)(k0 + 16 + qr) * ND);
        }
#pragma unroll
        for (int kk = 0; kk < 16; kk += 8) {
            unsigned af[2][4], qf[4][2], mf[4][2];
#pragma unroll
            for (int mi = 0; mi < 2; ++mi) {
                int m = mbase + mi * 16 + g;
                af[mi][0] = ldu(&As[p][kk + t][m]);     af[mi][1] = ldu(&As[p][kk + t][m + 8]);
                af[mi][2] = ldu(&As[p][kk + t + 4][m]); af[mi][3] = ldu(&As[p][kk + t + 4][m + 8]);
            }
#pragma unroll
            for (int ni = 0; ni < 4; ++ni) {
                int n = nbase + ni * 8 + g;
                qf[ni][0] = ldu(&Bq[p][kk + t][n]); qf[ni][1] = ldu(&Bq[p][kk + t + 4][n]);
                mf[ni][0] = ldu(&Bm[p][kk + t][n]); mf[ni][1] = ldu(&Bm[p][kk + t + 4][n]);
            }
#pragma unroll
            for (int mi = 0; mi < 2; ++mi)
#pragma unroll
                for (int ni = 0; ni < 4; ++ni) {
                    mma8(accA[mi][ni], af[mi][0], af[mi][1], af[mi][2], af[mi][3],
                         qf[ni][0], qf[ni][1]);
                    mma8(accB[mi][ni], af[mi][0], af[mi][1], af[mi][2], af[mi][3],
                         mf[ni][0], mf[ni][1]);
                }
        }
        if (nxt) {
            const int q2 = p ^ 1;
            As[q2][lks + 0][lrow] = f2tf(pa0.x); As[q2][lks + 1][lrow] = f2tf(pa0.y);
            As[q2][lks + 2][lrow] = f2tf(pa0.z); As[q2][lks + 3][lrow] = f2tf(pa0.w);
            As[q2][lks + 4][lrow] = f2tf(pa1.x); As[q2][lks + 5][lrow] = f2tf(pa1.y);
            As[q2][lks + 6][lrow] = f2tf(pa1.z); As[q2][lks + 7][lrow] = f2tf(pa1.w);
            *(float4*)&Bq[q2][qr][dl] = make_float4(f2tf(pq.x), f2tf(pq.y), f2tf(pq.z), f2tf(pq.w));
            *(float4*)&Bm[q2][qr][dl] = make_float4(f2tf(pm.x), f2tf(pm.y), f2tf(pm.z), f2tf(pm.w));
        }
        __syncthreads();
        p ^= 1;
    }
#pragma unroll
    for (int mi = 0; mi < 2; ++mi) {
        int cA = c0 + mbase + mi * 16 + g;
        float i0 = g_invrs[b * LCc + cA];
        float i1 = g_invrs[b * LCc + cA + 8];
#pragma unroll
        for (int ni = 0; ni < 4; ++ni) {
            accA[mi][ni].x *= i0; accA[mi][ni].y *= i0;
            accA[mi][ni].z *= i1; accA[mi][ni].w *= i1;
            accB[mi][ni].x *= i0; accB[mi][ni].y *= i0;
            accB[mi][ni].z *= i1; accB[mi][ni].w *= i1;
        }
    }
    const int cl = tid & 63, dseg = (tid >> 6) * 16;
    const int cr = tid & 63, db = tid >> 6;
    const size_t ob = (size_t)b * (4 * ND) * LCc;
    for (int h = 0; h < 2; ++h) {
        __syncthreads();
        {
            const float* Cg = C + (size_t)(c0 + h * 64 + cl) * (NB * ND) + (size_t)b * ND + d0 + dseg;
#pragma unroll
            for (int dd = 0; dd < 16; dd += 4) {
                float4 cv = *(const float4*)(Cg + dd);
                Cs[dseg + dd + 0][cl] = cv.x; Cs[dseg + dd + 1][cl] = cv.y;
                Cs[dseg + dd + 2][cl] = cv.z; Cs[dseg + dd + 3][cl] = cv.w;
            }
        }
        if ((w >> 2) == h) {
#pragma unroll
            for (int mi = 0; mi < 2; ++mi) {
                int clh = (wr & 1) * 32 + mi * 16 + g;
#pragma unroll
                for (int ni = 0; ni < 4; ++ni) {
                    int d = nbase + ni * 8 + 2 * t;
                    Tr[clh][d] = accA[mi][ni].x;     Tr[clh][d + 1] = accA[mi][ni].y;
                    Tr[clh + 8][d] = accA[mi][ni].z; Tr[clh + 8][d + 1] = accA[mi][ni].w;
                }
            }
        }
        __syncthreads();
#pragma unroll
        for (int rr = 0; rr < 16; ++rr) {
            int dr = db + rr * 4;
            float cval = Cs[dr][cr];
            float aval = Tr[cr][dr];
            size_t col = (size_t)(c0 + h * 64 + cr);
            out[ob + (size_t)(d0 + dr) * LCc + col]          = cval;
            out[ob + (size_t)(ND + d0 + dr) * LCc + col]     = aval;
            out[ob + (size_t)(2 * ND + d0 + dr) * LCc + col] = cval * aval;
        }
        __syncthreads();
        if ((w >> 2) == h) {
#pragma unroll
            for (int mi = 0; mi < 2; ++mi) {
                int clh = (wr & 1) * 32 + mi * 16 + g;
#pragma unroll
                for (int ni = 0; ni < 4; ++ni) {
                    int d = nbase + ni * 8 + 2 * t;
                    Tr[clh][d] = accB[mi][ni].x;     Tr[clh][d + 1] = accB[mi][ni].y;
                    Tr[clh + 8][d] = accB[mi][ni].z; Tr[clh + 8][d + 1] = accB[mi][ni].w;
                }
            }
        }
        __syncthreads();
#pragma unroll
        for (int rr = 0; rr < 16; ++rr) {
            int dr = db + rr * 4;
            out[ob + (size_t)(3 * ND + d0 + dr) * LCc + (size_t)(c0 + h * 64 + cr)] =
                Cs[dr][cr] * Tr[cr][dr];
        }
    }
}

extern "C" void kernel_launch(void* const* d_in, const int* in_sizes, int n_in,
                              void* d_out, int out_size) {
    const float* C     = (const float*)d_in[0];
    const float* Q     = (const float*)d_in[1];
    const float* w4C   = (const float*)d_in[2];
    const float* w4Q   = (const float*)d_in[3];
    const float* w4mlu = (const float*)d_in[4];
    const float* bias  = (const float*)d_in[5];
    float* out = (float*)d_out;

    k_init<<<(NB * LCc + 255) / 256, 256>>>();
    k0_sub<<<(NB * LCc + NB * LQq) / 8, 256>>>(C, Q, w4C, w4Q);
    k1_scores<<<dim3(LQq / 128, LCc / 128, NB), 256>>>(C, Q, w4mlu, bias);
    k_fin<<<(NB * LCc + 255) / 256, 256>>>();
    k4_M<<<dim3(ND / 128, LQq / 128, NB), 256>>>(C);
    k5_out<<<dim3(ND / 64, LCc / 128, NB), 256>>>(C, Q, out);
}